// round 8
// baseline (speedup 1.0000x reference)
#include <cuda_runtime.h>
#include <cuda_fp16.h>
#include <cstdint>

// ============================================================
// DST-II y[16384,1024] via Cooley-Tukey split n = 32a + b:
//  Stage1: P/Q[rp][b] = sum_a x[32a+b] * {sin,cos}(pi a rp/32), rp in [0,32]
//  Stage2 (residue form): for r = m mod 64 (r in 1..64), rp = min(r,64-r),
//    y[64c + r] = sum_b P[rp][b]*(sgnP cosB) + Q[rp][b]*sinB,  sgnP = (r<=32)?+1:-1
// R8: warp owns 8 consecutive residues -> float4 direct gmem stores,
//     NO y staging, NO copy-out, fp32 output precision.
// ============================================================

#define BATCH   16384
#define SIGS    16
#define THREADS 256

// smem layout (bytes)
#define SM_X    0          // x: [s16][a32][b32] fp16 pitch 80 = 40960 B
#define SM_PQ   40960      // [rp33]{[s16] rows of 128B, XOR-chunk swizzle}, pitch 2064
#define SMEM_TOTAL 109072

// gmem scratch (pre-packed mma fragments)
__device__ uint4 g_Wf[5 * 2 * 32];      // [mi5][ks2][lane32] A-fragments of W
__device__ uint4 g_B2n[64 * 4 * 32];    // [r-1][nj*2+ksh][lane32] B-fragments

// ---------------- helpers ----------------
__device__ __forceinline__ uint32_t smem_u32(const void* p) {
    uint32_t a;
    asm("{ .reg .u64 t; cvta.to.shared.u64 t, %1; cvt.u32.u64 %0, t; }" : "=r"(a) : "l"(p));
    return a;
}
__device__ __forceinline__ void ldm_x4(uint32_t* r, uint32_t addr) {
    asm volatile("ldmatrix.sync.aligned.m8n8.x4.shared.b16 {%0,%1,%2,%3}, [%4];\n"
                 : "=r"(r[0]), "=r"(r[1]), "=r"(r[2]), "=r"(r[3]) : "r"(addr));
}
__device__ __forceinline__ void ldm_x4_t(uint32_t* r, uint32_t addr) {
    asm volatile("ldmatrix.sync.aligned.m8n8.x4.trans.shared.b16 {%0,%1,%2,%3}, [%4];\n"
                 : "=r"(r[0]), "=r"(r[1]), "=r"(r[2]), "=r"(r[3]) : "r"(addr));
}
__device__ __forceinline__ void mma_16816(float* c, const uint32_t* a, const uint32_t* b) {
    asm volatile(
        "mma.sync.aligned.m16n8k16.row.col.f32.f16.f16.f32 "
        "{%0,%1,%2,%3}, {%4,%5,%6,%7}, {%8,%9}, {%0,%1,%2,%3};\n"
        : "+f"(c[0]), "+f"(c[1]), "+f"(c[2]), "+f"(c[3])
        : "r"(a[0]), "r"(a[1]), "r"(a[2]), "r"(a[3]), "r"(b[0]), "r"(b[1]));
}
__device__ __forceinline__ void sts32(uint32_t addr, uint32_t v) {
    asm volatile("st.shared.b32 [%0], %1;\n" :: "r"(addr), "r"(v));
}
__device__ __forceinline__ uint32_t pk2(float a, float b) {
    __half2 h = __floats2half2_rn(a, b);
    return *reinterpret_cast<uint32_t*>(&h);
}

// ============================================================
// Basis values
// ============================================================
__device__ __forceinline__ float w_val(int f, int a) {  // f = 2rp+pq
    int rp = f >> 1, pq = f & 1;
    if (rp > 32) return 0.0f;
    int mm = pq ? ((a * rp + 16) & 63) : ((a * rp) & 63);
    return sinpif((float)mm * (1.0f / 32.0f));
}
// stage-2 residue basis: r in 1..64, col in 0..15, q = pq*32 + b
__device__ __forceinline__ float b2n_val(int r, int col, int q) {
    int m = 64 * col + r;
    int b = q & 31, pq = q >> 5;
    int ang = ((2 * b + 1) * m) & 4095;
    if (pq == 0) {
        float sgn = (r <= 32) ? 1.0f : -1.0f;
        return sgn * sinpif((float)((ang + 1024) & 4095) * (1.0f / 2048.0f));
    }
    return sinpif((float)ang * (1.0f / 2048.0f));
}

__global__ void build_basis_kernel() {
    int bid = blockIdx.x;
    int tid = threadIdx.x;
    if (bid == 0) {
        if (tid < 320) {
            int mi = tid >> 6, ks = (tid >> 5) & 1, l = tid & 31;
            int r0 = l >> 2, k0 = 16 * ks + 2 * (l & 3);
            uint4 o;
            o.x = pk2(w_val(mi * 16 + r0,     k0),     w_val(mi * 16 + r0,     k0 + 1));
            o.y = pk2(w_val(mi * 16 + 8 + r0, k0),     w_val(mi * 16 + 8 + r0, k0 + 1));
            o.z = pk2(w_val(mi * 16 + r0,     k0 + 8), w_val(mi * 16 + r0,     k0 + 9));
            o.w = pk2(w_val(mi * 16 + 8 + r0, k0 + 8), w_val(mi * 16 + 8 + r0, k0 + 9));
            g_Wf[(mi * 2 + ks) * 32 + l] = o;
        }
    } else {
        int r = bid;   // residue 1..64
        if (tid < 128) {
            int f2 = tid >> 5, t = tid & 31;
            int nj = f2 >> 1, ksh = f2 & 1;
            int col = nj * 8 + (t >> 2);
            int q0 = (2 * ksh) * 16 + 2 * (t & 3);
            int q1 = q0 + 16;
            uint4 o;
            o.x = pk2(b2n_val(r, col, q0),     b2n_val(r, col, q0 + 1));
            o.y = pk2(b2n_val(r, col, q0 + 8), b2n_val(r, col, q0 + 9));
            o.z = pk2(b2n_val(r, col, q1),     b2n_val(r, col, q1 + 1));
            o.w = pk2(b2n_val(r, col, q1 + 8), b2n_val(r, col, q1 + 9));
            g_B2n[(r - 1) * 128 + f2 * 32 + t] = o;
        }
    }
}

// ============================================================
// Main fused kernel: 16 signals / CTA, 256 threads (8 warps), 2 CTAs/SM.
// ============================================================
__global__ void __launch_bounds__(THREADS, 2)
dst_fused_kernel(const float* __restrict__ x, float* __restrict__ y) {
    extern __shared__ char smem[];
    const uint32_t sb = smem_u32(smem);
    const int tid  = threadIdx.x;
    const int wid  = tid >> 5;
    const int lane = tid & 31;
    const int jj   = lane >> 3;
    const int ri   = lane & 7;
    const size_t s_base = (size_t)blockIdx.x * SIGS;

    // ---- x fp32 -> fp16 smem [s][a][b] pitch 80 ----
    #pragma unroll
    for (int i = 0; i < 16; i++) {
        int idx = i * THREADS + tid;            // 0..4095
        int s = idx >> 8;
        int n = (idx & 255) * 4;
        int a = n >> 5, b = n & 31;
        float4 v = *reinterpret_cast<const float4*>(x + (s_base + s) * 1024 + n);
        uint2 pk;
        pk.x = pk2(v.x, v.y);
        pk.y = pk2(v.z, v.w);
        *reinterpret_cast<uint2*>(smem + SM_X + s * 2560 + a * 80 + b * 2) = pk;
    }

    // ---- W A-fragments -> regs (L2-hot ldg) ----
    uint4 Wf[10];
    {
        const uint4* p = g_Wf + lane;
        #pragma unroll
        for (int f = 0; f < 10; f++) Wf[f] = __ldg(p + f * 32);
    }

    __syncthreads();

    // ================= Stage 1: warp = 2 signals =================
    const int g = lane >> 2, t4 = lane & 3;
    #pragma unroll
    for (int ss = 0; ss < 2; ss++) {
        const int s = wid * 2 + ss;
        uint32_t bf[2][4][2];
        #pragma unroll
        for (int ks = 0; ks < 2; ks++)
            #pragma unroll
            for (int n16 = 0; n16 < 2; n16++) {
                int a = ks * 16 + (lane & 15);
                uint32_t addr = sb + SM_X + (uint32_t)(s * 2560 + a * 80
                              + (n16 * 16 + (lane >> 4) * 8) * 2);
                uint32_t t[4];
                ldm_x4_t(t, addr);
                bf[ks][n16 * 2 + 0][0] = t[0]; bf[ks][n16 * 2 + 0][1] = t[1];
                bf[ks][n16 * 2 + 1][0] = t[2]; bf[ks][n16 * 2 + 1][1] = t[3];
            }
        #pragma unroll
        for (int mi = 0; mi < 5; mi++) {
            float acc[4][4];
            #pragma unroll
            for (int n8 = 0; n8 < 4; n8++)
                #pragma unroll
                for (int q = 0; q < 4; q++) acc[n8][q] = 0.0f;
            #pragma unroll
            for (int ks = 0; ks < 2; ks++) {
                uint32_t af[4] = { Wf[mi * 2 + ks].x, Wf[mi * 2 + ks].y,
                                   Wf[mi * 2 + ks].z, Wf[mi * 2 + ks].w };
                #pragma unroll
                for (int n8 = 0; n8 < 4; n8++)
                    mma_16816(acc[n8], af, bf[ks][n8]);
            }
            // packed conflict-free scatter to PQ[rp][s][q = pq*32 + b]
            #pragma unroll
            for (int n8 = 0; n8 < 4; n8++)
                #pragma unroll
                for (int ch = 0; ch < 2; ch++) {
                    int f = mi * 16 + g + (ch << 3);
                    if (f < 66) {
                        int b  = n8 * 8 + 2 * t4;        // even
                        int rp = f >> 1, pq = f & 1;
                        int u  = pq * 64 + 2 * b;        // byte offset, 4-aligned
                        uint32_t addr = sb + SM_PQ + (uint32_t)(rp * 2064 + s * 128
                                      + (((u >> 4) ^ (s & 7)) << 4) + (u & 15));
                        sts32(addr, pk2(acc[n8][2 * ch], acc[n8][2 * ch + 1]));
                    }
                }
        }
    }

    // prefetch first residue's B fragments (independent of PQ barrier)
    uint4 Bc[2][2];
    {
        const uint4* p = g_B2n + (size_t)(8 * wid) * 128 + lane;
        Bc[0][0] = __ldg(p);      Bc[0][1] = __ldg(p + 32);
        Bc[1][0] = __ldg(p + 64); Bc[1][1] = __ldg(p + 96);
    }

    __syncthreads();   // PQ complete

    // ================= Stage 2: residues r = 8*wid+1 .. 8*wid+8 =================
    #pragma unroll
    for (int h = 0; h < 2; h++) {
        float acc[4][2][4];
        #pragma unroll
        for (int e = 0; e < 4; e++)
            #pragma unroll
            for (int nj = 0; nj < 2; nj++)
                #pragma unroll
                for (int q = 0; q < 4; q++) acc[e][nj][q] = 0.0f;

        #pragma unroll
        for (int e = 0; e < 4; e++) {
            int idx = h * 4 + e;
            int r   = 8 * wid + idx + 1;
            int rp  = (r <= 32) ? r : 64 - r;

            // A = PQ[rp]: 16s x 64q
            uint32_t pqb = sb + SM_PQ + (uint32_t)(rp * 2064);
            uint32_t a2[4][4];
            #pragma unroll
            for (int ks = 0; ks < 4; ks++) {
                int sr = ((jj & 1) << 3) + ri;
                int c  = ks * 2 + (jj >> 1);
                ldm_x4(a2[ks], pqb + (uint32_t)(sr * 128 + ((c ^ (sr & 7)) << 4)));
            }

            // prefetch next residue's B
            uint4 Bn[2][2];
            if (idx < 7) {
                const uint4* p = g_B2n + (size_t)(8 * wid + idx + 1) * 128 + lane;
                Bn[0][0] = __ldg(p);      Bn[0][1] = __ldg(p + 32);
                Bn[1][0] = __ldg(p + 64); Bn[1][1] = __ldg(p + 96);
            }

            #pragma unroll
            for (int nj = 0; nj < 2; nj++) {
                uint32_t b0[2] = { Bc[nj][0].x, Bc[nj][0].y };
                mma_16816(acc[e][nj], a2[0], b0);
                uint32_t b1[2] = { Bc[nj][0].z, Bc[nj][0].w };
                mma_16816(acc[e][nj], a2[1], b1);
                uint32_t b2[2] = { Bc[nj][1].x, Bc[nj][1].y };
                mma_16816(acc[e][nj], a2[2], b2);
                uint32_t b3[2] = { Bc[nj][1].z, Bc[nj][1].w };
                mma_16816(acc[e][nj], a2[3], b3);
            }
            if (idx < 7) {
                #pragma unroll
                for (int nj = 0; nj < 2; nj++)
                    #pragma unroll
                    for (int kk = 0; kk < 2; kk++) Bc[nj][kk] = Bn[nj][kk];
            }
        }

        // direct float4 stores: M = 64*col + 8*wid + 4*h + e, e = 0..3
        #pragma unroll
        for (int nj = 0; nj < 2; nj++)
            #pragma unroll
            for (int cc = 0; cc < 4; cc++) {
                int col = nj * 8 + 2 * t4 + (cc & 1);
                int s   = g + ((cc >> 1) << 3);
                int M0  = 64 * col + 8 * wid + 4 * h;
                float4 v = make_float4(acc[0][nj][cc], acc[1][nj][cc],
                                       acc[2][nj][cc], acc[3][nj][cc]);
                *reinterpret_cast<float4*>(y + (s_base + s) * 1024 + M0) = v;
            }
    }
}

// ============================================================
// Launch
// ============================================================
extern "C" void kernel_launch(void* const* d_in, const int* in_sizes, int n_in,
                              void* d_out, int out_size) {
    const float* x = (const float*)d_in[0];
    float* y = (float*)d_out;

    build_basis_kernel<<<65, 512>>>();

    cudaFuncSetAttribute(dst_fused_kernel,
                         cudaFuncAttributeMaxDynamicSharedMemorySize, SMEM_TOTAL);
    dst_fused_kernel<<<BATCH / SIGS, THREADS, SMEM_TOTAL>>>(x, y);
}

// round 9
// speedup vs baseline: 1.1649x; 1.1649x over previous
#include <cuda_runtime.h>
#include <cuda_fp16.h>
#include <cstdint>

// ============================================================
// DST-II y[16384,1024] via Cooley-Tukey split n = 32a + b:
//  Stage1: P/Q[rp][b] = sum_a x[32a+b] * {sin,cos}(pi a rp/32), rp in [0,32]
//  Stage2 (residue form): r = m mod 64 (1..64), rp = min(r,64-r):
//    y[64c + r] = P[rp]*(sgnP cosB) + Q[rp]*sinB, sgnP = (r<=32)?+1:-1
// R9: warp owns 8 consecutive residues; 8 consecutive m per lane packed
//     fp16 -> st.shared.v4 (floor), swizzled staging, coalesced copy-out.
// ============================================================

#define BATCH   16384
#define SIGS    16
#define THREADS 256

// smem layout (bytes)
#define SM_X    0          // x: [s16][a32][b32] fp16 pitch 80 = 40960 B; later y-staging fp16 [s16][128 chunks x16B] = 32768 B
#define SM_PQ   40960      // [rp33]{[s16] rows of 128B, XOR-chunk swizzle}, pitch 2064
#define SMEM_TOTAL 109072

// gmem scratch (pre-packed mma fragments)
__device__ uint4 g_Wf[5 * 2 * 32];      // [mi5][ks2][lane32] A-fragments of W
__device__ uint4 g_B2n[64 * 4 * 32];    // [r-1][nj*2+ksh][lane32] B-fragments

// ---------------- helpers ----------------
__device__ __forceinline__ uint32_t smem_u32(const void* p) {
    uint32_t a;
    asm("{ .reg .u64 t; cvta.to.shared.u64 t, %1; cvt.u32.u64 %0, t; }" : "=r"(a) : "l"(p));
    return a;
}
__device__ __forceinline__ void ldm_x4(uint32_t* r, uint32_t addr) {
    asm volatile("ldmatrix.sync.aligned.m8n8.x4.shared.b16 {%0,%1,%2,%3}, [%4];\n"
                 : "=r"(r[0]), "=r"(r[1]), "=r"(r[2]), "=r"(r[3]) : "r"(addr));
}
__device__ __forceinline__ void ldm_x4_t(uint32_t* r, uint32_t addr) {
    asm volatile("ldmatrix.sync.aligned.m8n8.x4.trans.shared.b16 {%0,%1,%2,%3}, [%4];\n"
                 : "=r"(r[0]), "=r"(r[1]), "=r"(r[2]), "=r"(r[3]) : "r"(addr));
}
__device__ __forceinline__ void mma_16816(float* c, const uint32_t* a, const uint32_t* b) {
    asm volatile(
        "mma.sync.aligned.m16n8k16.row.col.f32.f16.f16.f32 "
        "{%0,%1,%2,%3}, {%4,%5,%6,%7}, {%8,%9}, {%0,%1,%2,%3};\n"
        : "+f"(c[0]), "+f"(c[1]), "+f"(c[2]), "+f"(c[3])
        : "r"(a[0]), "r"(a[1]), "r"(a[2]), "r"(a[3]), "r"(b[0]), "r"(b[1]));
}
__device__ __forceinline__ void sts32(uint32_t addr, uint32_t v) {
    asm volatile("st.shared.b32 [%0], %1;\n" :: "r"(addr), "r"(v));
}
__device__ __forceinline__ void sts128(uint32_t addr, uint32_t a, uint32_t b,
                                       uint32_t c, uint32_t d) {
    asm volatile("st.shared.v4.b32 [%0], {%1,%2,%3,%4};\n"
                 :: "r"(addr), "r"(a), "r"(b), "r"(c), "r"(d));
}
__device__ __forceinline__ void lds64(uint32_t addr, uint32_t& lo, uint32_t& hi) {
    asm volatile("ld.shared.v2.b32 {%0,%1}, [%2];\n" : "=r"(lo), "=r"(hi) : "r"(addr));
}
__device__ __forceinline__ uint32_t pk2(float a, float b) {
    __half2 h = __floats2half2_rn(a, b);
    return *reinterpret_cast<uint32_t*>(&h);
}

// ============================================================
// Basis values
// ============================================================
__device__ __forceinline__ float w_val(int f, int a) {  // f = 2rp+pq
    int rp = f >> 1, pq = f & 1;
    if (rp > 32) return 0.0f;
    int mm = pq ? ((a * rp + 16) & 63) : ((a * rp) & 63);
    return sinpif((float)mm * (1.0f / 32.0f));
}
// stage-2 residue basis: r in 1..64, col in 0..15, q = pq*32 + b
__device__ __forceinline__ float b2n_val(int r, int col, int q) {
    int m = 64 * col + r;
    int b = q & 31, pq = q >> 5;
    int ang = ((2 * b + 1) * m) & 4095;
    if (pq == 0) {
        float sgn = (r <= 32) ? 1.0f : -1.0f;
        return sgn * sinpif((float)((ang + 1024) & 4095) * (1.0f / 2048.0f));
    }
    return sinpif((float)ang * (1.0f / 2048.0f));
}

__global__ void build_basis_kernel() {
    int bid = blockIdx.x;
    int tid = threadIdx.x;
    if (bid == 0) {
        if (tid < 320) {
            int mi = tid >> 6, ks = (tid >> 5) & 1, l = tid & 31;
            int r0 = l >> 2, k0 = 16 * ks + 2 * (l & 3);
            uint4 o;
            o.x = pk2(w_val(mi * 16 + r0,     k0),     w_val(mi * 16 + r0,     k0 + 1));
            o.y = pk2(w_val(mi * 16 + 8 + r0, k0),     w_val(mi * 16 + 8 + r0, k0 + 1));
            o.z = pk2(w_val(mi * 16 + r0,     k0 + 8), w_val(mi * 16 + r0,     k0 + 9));
            o.w = pk2(w_val(mi * 16 + 8 + r0, k0 + 8), w_val(mi * 16 + 8 + r0, k0 + 9));
            g_Wf[(mi * 2 + ks) * 32 + l] = o;
        }
    } else {
        int r = bid;   // residue 1..64
        if (tid < 128) {
            int f2 = tid >> 5, t = tid & 31;
            int nj = f2 >> 1, ksh = f2 & 1;
            int col = nj * 8 + (t >> 2);
            int q0 = (2 * ksh) * 16 + 2 * (t & 3);
            int q1 = q0 + 16;
            uint4 o;
            o.x = pk2(b2n_val(r, col, q0),     b2n_val(r, col, q0 + 1));
            o.y = pk2(b2n_val(r, col, q0 + 8), b2n_val(r, col, q0 + 9));
            o.z = pk2(b2n_val(r, col, q1),     b2n_val(r, col, q1 + 1));
            o.w = pk2(b2n_val(r, col, q1 + 8), b2n_val(r, col, q1 + 9));
            g_B2n[(r - 1) * 128 + f2 * 32 + t] = o;
        }
    }
}

// ============================================================
// Main fused kernel: 16 signals / CTA, 256 threads (8 warps), 2 CTAs/SM.
// ============================================================
__global__ void __launch_bounds__(THREADS, 2)
dst_fused_kernel(const float* __restrict__ x, float* __restrict__ y) {
    extern __shared__ char smem[];
    const uint32_t sb = smem_u32(smem);
    const int tid  = threadIdx.x;
    const int wid  = tid >> 5;
    const int lane = tid & 31;
    const int jj   = lane >> 3;
    const int ri   = lane & 7;
    const size_t s_base = (size_t)blockIdx.x * SIGS;

    // ---- x fp32 -> fp16 smem [s][a][b] pitch 80 ----
    #pragma unroll
    for (int i = 0; i < 16; i++) {
        int idx = i * THREADS + tid;            // 0..4095
        int s = idx >> 8;
        int n = (idx & 255) * 4;
        int a = n >> 5, b = n & 31;
        float4 v = *reinterpret_cast<const float4*>(x + (s_base + s) * 1024 + n);
        uint2 pk;
        pk.x = pk2(v.x, v.y);
        pk.y = pk2(v.z, v.w);
        *reinterpret_cast<uint2*>(smem + SM_X + s * 2560 + a * 80 + b * 2) = pk;
    }

    // ---- W A-fragments -> regs (L2-hot ldg) ----
    uint4 Wf[10];
    {
        const uint4* p = g_Wf + lane;
        #pragma unroll
        for (int f = 0; f < 10; f++) Wf[f] = __ldg(p + f * 32);
    }

    __syncthreads();

    // ================= Stage 1: warp = 2 signals =================
    const int g = lane >> 2, t4 = lane & 3;
    #pragma unroll
    for (int ss = 0; ss < 2; ss++) {
        const int s = wid * 2 + ss;
        uint32_t bf[2][4][2];
        #pragma unroll
        for (int ks = 0; ks < 2; ks++)
            #pragma unroll
            for (int n16 = 0; n16 < 2; n16++) {
                int a = ks * 16 + (lane & 15);
                uint32_t addr = sb + SM_X + (uint32_t)(s * 2560 + a * 80
                              + (n16 * 16 + (lane >> 4) * 8) * 2);
                uint32_t t[4];
                ldm_x4_t(t, addr);
                bf[ks][n16 * 2 + 0][0] = t[0]; bf[ks][n16 * 2 + 0][1] = t[1];
                bf[ks][n16 * 2 + 1][0] = t[2]; bf[ks][n16 * 2 + 1][1] = t[3];
            }
        #pragma unroll
        for (int mi = 0; mi < 5; mi++) {
            float acc[4][4];
            #pragma unroll
            for (int n8 = 0; n8 < 4; n8++)
                #pragma unroll
                for (int q = 0; q < 4; q++) acc[n8][q] = 0.0f;
            #pragma unroll
            for (int ks = 0; ks < 2; ks++) {
                uint32_t af[4] = { Wf[mi * 2 + ks].x, Wf[mi * 2 + ks].y,
                                   Wf[mi * 2 + ks].z, Wf[mi * 2 + ks].w };
                #pragma unroll
                for (int n8 = 0; n8 < 4; n8++)
                    mma_16816(acc[n8], af, bf[ks][n8]);
            }
            // packed conflict-free scatter to PQ[rp][s][q = pq*32 + b]
            #pragma unroll
            for (int n8 = 0; n8 < 4; n8++)
                #pragma unroll
                for (int ch = 0; ch < 2; ch++) {
                    int f = mi * 16 + g + (ch << 3);
                    if (f < 66) {
                        int b  = n8 * 8 + 2 * t4;        // even
                        int rp = f >> 1, pq = f & 1;
                        int u  = pq * 64 + 2 * b;        // byte offset, 4-aligned
                        uint32_t addr = sb + SM_PQ + (uint32_t)(rp * 2064 + s * 128
                                      + (((u >> 4) ^ (s & 7)) << 4) + (u & 15));
                        sts32(addr, pk2(acc[n8][2 * ch], acc[n8][2 * ch + 1]));
                    }
                }
        }
    }

    // prefetch first residue's B fragments (independent of PQ barrier)
    uint4 Bc[2][2];
    {
        const uint4* p = g_B2n + (size_t)(8 * wid) * 128 + lane;
        Bc[0][0] = __ldg(p);      Bc[0][1] = __ldg(p + 32);
        Bc[1][0] = __ldg(p + 64); Bc[1][1] = __ldg(p + 96);
    }

    __syncthreads();   // PQ complete; x buffer dead -> y staging (fp16 chunks)

    // ================= Stage 2: residues r = 8*wid+1 .. 8*wid+8 =================
    uint32_t u0[2][4][2];   // packed fp16 pairs for h=0: [nj][cc][lohi]
    uint32_t u1[2][4][2];
    #pragma unroll
    for (int h = 0; h < 2; h++) {
        float acc[4][2][4];
        #pragma unroll
        for (int e = 0; e < 4; e++)
            #pragma unroll
            for (int nj = 0; nj < 2; nj++)
                #pragma unroll
                for (int q = 0; q < 4; q++) acc[e][nj][q] = 0.0f;

        #pragma unroll
        for (int e = 0; e < 4; e++) {
            int idx = h * 4 + e;
            int r   = 8 * wid + idx + 1;
            int rp  = (r <= 32) ? r : 64 - r;

            // A = PQ[rp]: 16s x 64q
            uint32_t pqb = sb + SM_PQ + (uint32_t)(rp * 2064);
            uint32_t a2[4][4];
            #pragma unroll
            for (int ks = 0; ks < 4; ks++) {
                int sr = ((jj & 1) << 3) + ri;
                int c  = ks * 2 + (jj >> 1);
                ldm_x4(a2[ks], pqb + (uint32_t)(sr * 128 + ((c ^ (sr & 7)) << 4)));
            }

            // prefetch next residue's B
            uint4 Bn[2][2];
            if (idx < 7) {
                const uint4* p = g_B2n + (size_t)(8 * wid + idx + 1) * 128 + lane;
                Bn[0][0] = __ldg(p);      Bn[0][1] = __ldg(p + 32);
                Bn[1][0] = __ldg(p + 64); Bn[1][1] = __ldg(p + 96);
            }

            #pragma unroll
            for (int nj = 0; nj < 2; nj++) {
                uint32_t b0[2] = { Bc[nj][0].x, Bc[nj][0].y };
                mma_16816(acc[e][nj], a2[0], b0);
                uint32_t b1[2] = { Bc[nj][0].z, Bc[nj][0].w };
                mma_16816(acc[e][nj], a2[1], b1);
                uint32_t b2[2] = { Bc[nj][1].x, Bc[nj][1].y };
                mma_16816(acc[e][nj], a2[2], b2);
                uint32_t b3[2] = { Bc[nj][1].z, Bc[nj][1].w };
                mma_16816(acc[e][nj], a2[3], b3);
            }
            if (idx < 7) {
                #pragma unroll
                for (int nj = 0; nj < 2; nj++)
                    #pragma unroll
                    for (int kk = 0; kk < 2; kk++) Bc[nj][kk] = Bn[nj][kk];
            }
        }

        // pack h-half to fp16: lane (nj, cc) covers m = 64col + 8wid + 4h + e
        #pragma unroll
        for (int nj = 0; nj < 2; nj++)
            #pragma unroll
            for (int cc = 0; cc < 4; cc++) {
                uint32_t lo = pk2(acc[0][nj][cc], acc[1][nj][cc]);
                uint32_t hi = pk2(acc[2][nj][cc], acc[3][nj][cc]);
                if (h == 0) { u0[nj][cc][0] = lo; u0[nj][cc][1] = hi; }
                else        { u1[nj][cc][0] = lo; u1[nj][cc][1] = hi; }
            }
    }

    // store staged chunks: chunk L = 8col + wid, phys = L ^ (s&7), 16B each
    #pragma unroll
    for (int nj = 0; nj < 2; nj++)
        #pragma unroll
        for (int cc = 0; cc < 4; cc++) {
            int col = nj * 8 + 2 * t4 + (cc & 1);
            int s   = g + ((cc >> 1) << 3);
            uint32_t L = (uint32_t)(8 * col + wid);
            uint32_t phys = L ^ (uint32_t)(s & 7);
            sts128(sb + SM_X + (uint32_t)(s * 2048) + phys * 16,
                   u0[nj][cc][0], u0[nj][cc][1], u1[nj][cc][0], u1[nj][cc][1]);
        }

    __syncthreads();

    // ---- copy-out: fp16 staging -> fp32 gmem, fully coalesced ----
    #pragma unroll
    for (int i = 0; i < 16; i++) {
        int flat = i * THREADS + tid;           // 0..4095 float4 index
        int s  = flat >> 8;
        int f4 = flat & 255;
        uint32_t L = (uint32_t)(f4 >> 1);
        uint32_t half = (uint32_t)(f4 & 1);
        uint32_t phys = L ^ (uint32_t)(s & 7);
        uint32_t lo, hi;
        lds64(sb + SM_X + (uint32_t)(s * 2048) + phys * 16 + half * 8, lo, hi);
        __half2 hl = *reinterpret_cast<__half2*>(&lo);
        __half2 hh = *reinterpret_cast<__half2*>(&hi);
        float2 f0 = __half22float2(hl);
        float2 f1 = __half22float2(hh);
        float4 v = make_float4(f0.x, f0.y, f1.x, f1.y);
        *reinterpret_cast<float4*>(y + (s_base + s) * 1024 + f4 * 4) = v;
    }
}

// ============================================================
// Launch
// ============================================================
extern "C" void kernel_launch(void* const* d_in, const int* in_sizes, int n_in,
                              void* d_out, int out_size) {
    const float* x = (const float*)d_in[0];
    float* y = (float*)d_out;

    build_basis_kernel<<<65, 512>>>();

    cudaFuncSetAttribute(dst_fused_kernel,
                         cudaFuncAttributeMaxDynamicSharedMemorySize, SMEM_TOTAL);
    dst_fused_kernel<<<BATCH / SIGS, THREADS, SMEM_TOTAL>>>(x, y);
}

// round 10
// speedup vs baseline: 1.1657x; 1.0006x over previous
#include <cuda_runtime.h>
#include <cuda_fp16.h>
#include <cstdint>

// ============================================================
// DST-II y[16384,1024] via Cooley-Tukey split n = 32a + b:
//  Stage1: P/Q[rp][b] = sum_a x[32a+b] * {sin,cos}(pi a rp/32), rp in [0,32]
//  Stage2 (residue form): r = m mod 64 (1..64), rp = min(r,64-r):
//    y[64c + r] = P[rp]*(sgnP cosB) + Q[rp]*sinB, sgnP = (r<=32)?+1:-1
// R10: per-warp x pipeline (no CTA barrier before stage 1),
//      f-compaction (P[0]=P[32]=0 removed -> 4 mi tiles, no predicates),
//      residue stage-2 + v4 fp16 staging + coalesced copy-out (from R9).
// ============================================================

#define BATCH   16384
#define SIGS    16
#define THREADS 256

// smem layout (bytes)
#define SM_X    0          // x: [s16][a32][b32] fp16 pitch 80 = 40960 B; later y-staging fp16 [s16][128 chunks x16B]
#define SM_PQ   40960      // [rp33]{[s16] rows of 128B, XOR-chunk swizzle}, pitch 2064
#define SMEM_TOTAL 109072

// gmem scratch (pre-packed mma fragments)
__device__ uint4 g_Wf[4 * 2 * 32];      // [mi4][ks2][lane32] A-fragments of compacted W
__device__ uint4 g_B2n[64 * 4 * 32];    // [r-1][nj*2+ksh][lane32] B-fragments

// ---------------- helpers ----------------
__device__ __forceinline__ uint32_t smem_u32(const void* p) {
    uint32_t a;
    asm("{ .reg .u64 t; cvta.to.shared.u64 t, %1; cvt.u32.u64 %0, t; }" : "=r"(a) : "l"(p));
    return a;
}
__device__ __forceinline__ void ldm_x4(uint32_t* r, uint32_t addr) {
    asm volatile("ldmatrix.sync.aligned.m8n8.x4.shared.b16 {%0,%1,%2,%3}, [%4];\n"
                 : "=r"(r[0]), "=r"(r[1]), "=r"(r[2]), "=r"(r[3]) : "r"(addr));
}
__device__ __forceinline__ void ldm_x4_t(uint32_t* r, uint32_t addr) {
    asm volatile("ldmatrix.sync.aligned.m8n8.x4.trans.shared.b16 {%0,%1,%2,%3}, [%4];\n"
                 : "=r"(r[0]), "=r"(r[1]), "=r"(r[2]), "=r"(r[3]) : "r"(addr));
}
__device__ __forceinline__ void mma_16816(float* c, const uint32_t* a, const uint32_t* b) {
    asm volatile(
        "mma.sync.aligned.m16n8k16.row.col.f32.f16.f16.f32 "
        "{%0,%1,%2,%3}, {%4,%5,%6,%7}, {%8,%9}, {%0,%1,%2,%3};\n"
        : "+f"(c[0]), "+f"(c[1]), "+f"(c[2]), "+f"(c[3])
        : "r"(a[0]), "r"(a[1]), "r"(a[2]), "r"(a[3]), "r"(b[0]), "r"(b[1]));
}
__device__ __forceinline__ void sts32(uint32_t addr, uint32_t v) {
    asm volatile("st.shared.b32 [%0], %1;\n" :: "r"(addr), "r"(v));
}
__device__ __forceinline__ void sts128(uint32_t addr, uint32_t a, uint32_t b,
                                       uint32_t c, uint32_t d) {
    asm volatile("st.shared.v4.b32 [%0], {%1,%2,%3,%4};\n"
                 :: "r"(addr), "r"(a), "r"(b), "r"(c), "r"(d));
}
__device__ __forceinline__ void lds64(uint32_t addr, uint32_t& lo, uint32_t& hi) {
    asm volatile("ld.shared.v2.b32 {%0,%1}, [%2];\n" : "=r"(lo), "=r"(hi) : "r"(addr));
}
__device__ __forceinline__ uint32_t pk2(float a, float b) {
    __half2 h = __floats2half2_rn(a, b);
    return *reinterpret_cast<uint32_t*>(&h);
}

// ============================================================
// Basis values
// ============================================================
__device__ __forceinline__ float w_val(int f, int a) {  // f = 2rp+pq
    int rp = f >> 1, pq = f & 1;
    if (rp > 32) return 0.0f;
    int mm = pq ? ((a * rp + 16) & 63) : ((a * rp) & 63);
    return sinpif((float)mm * (1.0f / 32.0f));
}
// compacted W row fp (0..63): fp<63 -> f=fp+1; fp=63 -> f=65 (Q[32])
__device__ __forceinline__ float w2_val(int fp, int a) {
    int f = (fp == 63) ? 65 : fp + 1;
    return w_val(f, a);
}
// stage-2 residue basis: r in 1..64, col in 0..15, q = pq*32 + b
__device__ __forceinline__ float b2n_val(int r, int col, int q) {
    int m = 64 * col + r;
    int b = q & 31, pq = q >> 5;
    int ang = ((2 * b + 1) * m) & 4095;
    if (pq == 0) {
        if (r == 32 || r == 64) return 0.0f;   // P[32]=P[0]=0 -> kill coefficient
        float sgn = (r <= 32) ? 1.0f : -1.0f;
        return sgn * sinpif((float)((ang + 1024) & 4095) * (1.0f / 2048.0f));
    }
    return sinpif((float)ang * (1.0f / 2048.0f));
}

__global__ void build_basis_kernel() {
    int bid = blockIdx.x;
    int tid = threadIdx.x;
    if (bid == 0) {
        if (tid < 256) {
            int mi = tid >> 6, ks = (tid >> 5) & 1, l = tid & 31;
            int r0 = l >> 2, k0 = 16 * ks + 2 * (l & 3);
            uint4 o;
            o.x = pk2(w2_val(mi * 16 + r0,     k0),     w2_val(mi * 16 + r0,     k0 + 1));
            o.y = pk2(w2_val(mi * 16 + 8 + r0, k0),     w2_val(mi * 16 + 8 + r0, k0 + 1));
            o.z = pk2(w2_val(mi * 16 + r0,     k0 + 8), w2_val(mi * 16 + r0,     k0 + 9));
            o.w = pk2(w2_val(mi * 16 + 8 + r0, k0 + 8), w2_val(mi * 16 + 8 + r0, k0 + 9));
            g_Wf[(mi * 2 + ks) * 32 + l] = o;
        }
    } else {
        int r = bid;   // residue 1..64
        if (tid < 128) {
            int f2 = tid >> 5, t = tid & 31;
            int nj = f2 >> 1, ksh = f2 & 1;
            int col = nj * 8 + (t >> 2);
            int q0 = (2 * ksh) * 16 + 2 * (t & 3);
            int q1 = q0 + 16;
            uint4 o;
            o.x = pk2(b2n_val(r, col, q0),     b2n_val(r, col, q0 + 1));
            o.y = pk2(b2n_val(r, col, q0 + 8), b2n_val(r, col, q0 + 9));
            o.z = pk2(b2n_val(r, col, q1),     b2n_val(r, col, q1 + 1));
            o.w = pk2(b2n_val(r, col, q1 + 8), b2n_val(r, col, q1 + 9));
            g_B2n[(r - 1) * 128 + f2 * 32 + t] = o;
        }
    }
}

// ============================================================
// Main fused kernel: 16 signals / CTA, 256 threads (8 warps), 2 CTAs/SM.
// ============================================================
__global__ void __launch_bounds__(THREADS, 2)
dst_fused_kernel(const float* __restrict__ x, float* __restrict__ y) {
    extern __shared__ char smem[];
    const uint32_t sb = smem_u32(smem);
    const int tid  = threadIdx.x;
    const int wid  = tid >> 5;
    const int lane = tid & 31;
    const int jj   = lane >> 3;
    const int ri   = lane & 7;
    const size_t s_base = (size_t)blockIdx.x * SIGS;

    // ---- W A-fragments -> regs (L2-hot ldg, overlaps x loads) ----
    uint4 Wf[8];
    {
        const uint4* p = g_Wf + lane;
        #pragma unroll
        for (int f = 0; f < 8; f++) Wf[f] = __ldg(p + f * 32);
    }

    // ---- per-warp x load: signals 2wid, 2wid+1 (fp32 -> fp16, pitch 80) ----
    #pragma unroll
    for (int ss = 0; ss < 2; ss++) {
        const int s = 2 * wid + ss;
        const float4* xs = reinterpret_cast<const float4*>(x + (s_base + s) * 1024);
        float4 xv[8];
        #pragma unroll
        for (int i = 0; i < 8; i++) xv[i] = xs[i * 32 + lane];
        #pragma unroll
        for (int i = 0; i < 8; i++) {
            int a = 4 * i + (lane >> 3), b = 4 * (lane & 7);
            uint2 pk;
            pk.x = pk2(xv[i].x, xv[i].y);
            pk.y = pk2(xv[i].z, xv[i].w);
            *reinterpret_cast<uint2*>(smem + SM_X + s * 2560 + a * 80 + b * 2) = pk;
        }
    }

    // ---- zero P-halves of PQ rows rp=0 and rp=32 for own signals ----
    {
        int L = lane & 15;
        int s = 2 * wid + (lane >> 4);
        uint32_t off = (uint32_t)(s * 128 + (((L >> 2) ^ (s & 7)) << 4) + 4 * (L & 3));
        sts32(sb + SM_PQ + off, 0u);              // rp = 0
        sts32(sb + SM_PQ + 32 * 2064 + off, 0u);  // rp = 32
    }

    __syncwarp();   // own x rows + zeros visible to this warp

    // ================= Stage 1: warp = 2 signals, 4 mi tiles =================
    const int g = lane >> 2, t4 = lane & 3;
    #pragma unroll
    for (int ss = 0; ss < 2; ss++) {
        const int s = 2 * wid + ss;
        uint32_t bf[2][4][2];
        #pragma unroll
        for (int ks = 0; ks < 2; ks++)
            #pragma unroll
            for (int n16 = 0; n16 < 2; n16++) {
                int a = ks * 16 + (lane & 15);
                uint32_t addr = sb + SM_X + (uint32_t)(s * 2560 + a * 80
                              + (n16 * 16 + (lane >> 4) * 8) * 2);
                uint32_t t[4];
                ldm_x4_t(t, addr);
                bf[ks][n16 * 2 + 0][0] = t[0]; bf[ks][n16 * 2 + 0][1] = t[1];
                bf[ks][n16 * 2 + 1][0] = t[2]; bf[ks][n16 * 2 + 1][1] = t[3];
            }
        #pragma unroll
        for (int mi = 0; mi < 4; mi++) {
            float acc[4][4];
            #pragma unroll
            for (int n8 = 0; n8 < 4; n8++)
                #pragma unroll
                for (int q = 0; q < 4; q++) acc[n8][q] = 0.0f;
            #pragma unroll
            for (int ks = 0; ks < 2; ks++) {
                uint32_t af[4] = { Wf[mi * 2 + ks].x, Wf[mi * 2 + ks].y,
                                   Wf[mi * 2 + ks].z, Wf[mi * 2 + ks].w };
                #pragma unroll
                for (int n8 = 0; n8 < 4; n8++)
                    mma_16816(acc[n8], af, bf[ks][n8]);
            }
            // unpredicated packed scatter: fp -> f = (fp==63)?65:fp+1
            #pragma unroll
            for (int n8 = 0; n8 < 4; n8++)
                #pragma unroll
                for (int ch = 0; ch < 2; ch++) {
                    int fp = mi * 16 + g + (ch << 3);
                    int f  = (fp == 63) ? 65 : fp + 1;
                    int b  = n8 * 8 + 2 * t4;        // even
                    int rp = f >> 1, pq = f & 1;
                    int u  = pq * 64 + 2 * b;        // byte offset, 4-aligned
                    uint32_t addr = sb + SM_PQ + (uint32_t)(rp * 2064 + s * 128
                                  + (((u >> 4) ^ (s & 7)) << 4) + (u & 15));
                    sts32(addr, pk2(acc[n8][2 * ch], acc[n8][2 * ch + 1]));
                }
        }
    }

    // prefetch first residue's B fragments (independent of PQ barrier)
    uint4 Bc[2][2];
    {
        const uint4* p = g_B2n + (size_t)(8 * wid) * 128 + lane;
        Bc[0][0] = __ldg(p);      Bc[0][1] = __ldg(p + 32);
        Bc[1][0] = __ldg(p + 64); Bc[1][1] = __ldg(p + 96);
    }

    __syncthreads();   // PQ complete; x buffer dead -> y staging (fp16 chunks)

    // ================= Stage 2: residues r = 8*wid+1 .. 8*wid+8 =================
    uint32_t u0[2][4][2];   // packed fp16 pairs for h=0: [nj][cc][lohi]
    uint32_t u1[2][4][2];
    #pragma unroll
    for (int h = 0; h < 2; h++) {
        float acc[4][2][4];
        #pragma unroll
        for (int e = 0; e < 4; e++)
            #pragma unroll
            for (int nj = 0; nj < 2; nj++)
                #pragma unroll
                for (int q = 0; q < 4; q++) acc[e][nj][q] = 0.0f;

        #pragma unroll
        for (int e = 0; e < 4; e++) {
            int idx = h * 4 + e;
            int r   = 8 * wid + idx + 1;
            int rp  = (r <= 32) ? r : 64 - r;

            // A = PQ[rp]: 16s x 64q
            uint32_t pqb = sb + SM_PQ + (uint32_t)(rp * 2064);
            uint32_t a2[4][4];
            #pragma unroll
            for (int ks = 0; ks < 4; ks++) {
                int sr = ((jj & 1) << 3) + ri;
                int c  = ks * 2 + (jj >> 1);
                ldm_x4(a2[ks], pqb + (uint32_t)(sr * 128 + ((c ^ (sr & 7)) << 4)));
            }

            // prefetch next residue's B
            uint4 Bn[2][2];
            if (idx < 7) {
                const uint4* p = g_B2n + (size_t)(8 * wid + idx + 1) * 128 + lane;
                Bn[0][0] = __ldg(p);      Bn[0][1] = __ldg(p + 32);
                Bn[1][0] = __ldg(p + 64); Bn[1][1] = __ldg(p + 96);
            }

            #pragma unroll
            for (int nj = 0; nj < 2; nj++) {
                uint32_t b0[2] = { Bc[nj][0].x, Bc[nj][0].y };
                mma_16816(acc[e][nj], a2[0], b0);
                uint32_t b1[2] = { Bc[nj][0].z, Bc[nj][0].w };
                mma_16816(acc[e][nj], a2[1], b1);
                uint32_t b2[2] = { Bc[nj][1].x, Bc[nj][1].y };
                mma_16816(acc[e][nj], a2[2], b2);
                uint32_t b3[2] = { Bc[nj][1].z, Bc[nj][1].w };
                mma_16816(acc[e][nj], a2[3], b3);
            }
            if (idx < 7) {
                #pragma unroll
                for (int nj = 0; nj < 2; nj++)
                    #pragma unroll
                    for (int kk = 0; kk < 2; kk++) Bc[nj][kk] = Bn[nj][kk];
            }
        }

        // pack h-half to fp16: lane (nj, cc) covers m = 64col + 8wid + 4h + e
        #pragma unroll
        for (int nj = 0; nj < 2; nj++)
            #pragma unroll
            for (int cc = 0; cc < 4; cc++) {
                uint32_t lo = pk2(acc[0][nj][cc], acc[1][nj][cc]);
                uint32_t hi = pk2(acc[2][nj][cc], acc[3][nj][cc]);
                if (h == 0) { u0[nj][cc][0] = lo; u0[nj][cc][1] = hi; }
                else        { u1[nj][cc][0] = lo; u1[nj][cc][1] = hi; }
            }
    }

    // store staged chunks: chunk L = 8col + wid, phys = L ^ (s&7), 16B each
    #pragma unroll
    for (int nj = 0; nj < 2; nj++)
        #pragma unroll
        for (int cc = 0; cc < 4; cc++) {
            int col = nj * 8 + 2 * t4 + (cc & 1);
            int s   = g + ((cc >> 1) << 3);
            uint32_t L = (uint32_t)(8 * col + wid);
            uint32_t phys = L ^ (uint32_t)(s & 7);
            sts128(sb + SM_X + (uint32_t)(s * 2048) + phys * 16,
                   u0[nj][cc][0], u0[nj][cc][1], u1[nj][cc][0], u1[nj][cc][1]);
        }

    __syncthreads();

    // ---- copy-out: fp16 staging -> fp32 gmem, fully coalesced ----
    #pragma unroll
    for (int i = 0; i < 16; i++) {
        int flat = i * THREADS + tid;           // 0..4095 float4 index
        int s  = flat >> 8;
        int f4 = flat & 255;
        uint32_t L = (uint32_t)(f4 >> 1);
        uint32_t half = (uint32_t)(f4 & 1);
        uint32_t phys = L ^ (uint32_t)(s & 7);
        uint32_t lo, hi;
        lds64(sb + SM_X + (uint32_t)(s * 2048) + phys * 16 + half * 8, lo, hi);
        __half2 hl = *reinterpret_cast<__half2*>(&lo);
        __half2 hh = *reinterpret_cast<__half2*>(&hi);
        float2 f0 = __half22float2(hl);
        float2 f1 = __half22float2(hh);
        float4 v = make_float4(f0.x, f0.y, f1.x, f1.y);
        *reinterpret_cast<float4*>(y + (s_base + s) * 1024 + f4 * 4) = v;
    }
}

// ============================================================
// Launch
// ============================================================
extern "C" void kernel_launch(void* const* d_in, const int* in_sizes, int n_in,
                              void* d_out, int out_size) {
    const float* x = (const float*)d_in[0];
    float* y = (float*)d_out;

    build_basis_kernel<<<65, 512>>>();

    cudaFuncSetAttribute(dst_fused_kernel,
                         cudaFuncAttributeMaxDynamicSharedMemorySize, SMEM_TOTAL);
    dst_fused_kernel<<<BATCH / SIGS, THREADS, SMEM_TOTAL>>>(x, y);
}